// round 3
// baseline (speedup 1.0000x reference)
#include <cuda_runtime.h>
#include <cuda_bf16.h>

// ---------------------------------------------------------------------------
// Decoder_65111704207909  (B=8192, T=20, H=128, K=5)
// Round 3: 2 CTAs/SM x 256 threads, 28 rows/CTA, grid=293 (one wave).
//  - triple-buffered cp.async U staging, ONE barrier per chunk
//  - encW packed pairwise -> LDG.64 acc init
//  - head weights / W-tail from L1 (smem diet); co-resident CTA hides latency
// ---------------------------------------------------------------------------

#define Bsz 8192
#define Tt 20
#define Hh 128
#define KcK 5
#define NG 512                    // 4*H
#define ROWS 28
#define NCTA 293
#define NTHREADS 256
#define HSTR 30                   // padded row stride (even, for u64 loads)
#define KCH 8                     // k-rows per staged chunk
#define NCHUNK (Hh / KCH)         // 16
#define PRE_BB 16

typedef unsigned long long u64;

// enc_h @ W[:H] + b (bias folded), pair-packed: [(b>>1)][col][b&1]
__device__ float g_encW_my[(size_t)Bsz * NG];
__device__ float g_encW_ff[(size_t)Bsz * NG];

__device__ __forceinline__ u64 pack2f(float x, float y) {
    u64 r; asm("mov.b64 %0, {%1, %2};" : "=l"(r) : "f"(x), "f"(y)); return r;
}
__device__ __forceinline__ u64 dup2f(float x) {
    u64 r; asm("mov.b64 %0, {%1, %1};" : "=l"(r) : "f"(x)); return r;
}
__device__ __forceinline__ void fma2(u64& d, u64 a, u64 b) {
    asm("fma.rn.f32x2 %0, %1, %2, %0;" : "+l"(d) : "l"(a), "l"(b));
}
__device__ __forceinline__ void unpack2(u64 v, float& x, float& y) {
    asm("mov.b64 {%0, %1}, %2;" : "=f"(x), "=f"(y) : "l"(v));
}

// ---- fast transcendentals ----
__device__ __forceinline__ float ex2f(float x) {
    float y; asm("ex2.approx.f32 %0, %1;" : "=f"(y) : "f"(x)); return y;
}
__device__ __forceinline__ float rcpf(float x) {
    float y; asm("rcp.approx.f32 %0, %1;" : "=f"(y) : "f"(x)); return y;
}
#define LOG2E 1.4426950408889634f
__device__ __forceinline__ float sigf(float x) {
    return rcpf(1.0f + ex2f(-LOG2E * x));
}
__device__ __forceinline__ float tanhf_fast(float x) {
    return fmaf(-2.0f, rcpf(1.0f + ex2f((2.0f * LOG2E) * x)), 1.0f);
}
__device__ __forceinline__ float expf_fast(float x) { return ex2f(LOG2E * x); }

// ---- cp.async helpers: one chunk = KCH*NG floats = 16KB, 256 thr x 4 x 16B ----
__device__ __forceinline__ void stage_chunk(float* dst, const float* __restrict__ src, int tid) {
    unsigned smp = (unsigned)__cvta_generic_to_shared(dst);
#pragma unroll
    for (int i = 0; i < 4; i++) {
        asm volatile("cp.async.cg.shared.global [%0], [%1], 16;"
                     :: "r"(smp + (unsigned)((tid + i * NTHREADS) * 16)),
                        "l"(src + (size_t)(tid + i * NTHREADS) * 4)
                     : "memory");
    }
    asm volatile("cp.async.commit_group;" ::: "memory");
}
template <int N>
__device__ __forceinline__ void cp_wait() {
    asm volatile("cp.async.wait_group %0;" :: "n"(N) : "memory");
}

// ---------------------------------------------------------------------------
// Precompute: g_encW = state_h @ W[:H, :] + b (both LSTMs), pair-packed layout
// ---------------------------------------------------------------------------
__global__ __launch_bounds__(256) void precompute_kernel(
    const float* __restrict__ state_h,
    const float* __restrict__ W_my, const float* __restrict__ b_my,
    const float* __restrict__ W_ff, const float* __restrict__ b_ff)
{
    __shared__ float hsh[Hh * PRE_BB];  // [k][bb]
    const int t = threadIdx.x;
    const int b0 = blockIdx.x * PRE_BB;

    for (int idx = t; idx < Hh * PRE_BB; idx += 256) {
        int k = idx / PRE_BB, bb = idx % PRE_BB;
        hsh[idx] = state_h[(size_t)(b0 + bb) * Hh + k];
    }
    __syncthreads();

    const int c0 = 2 * t;
    u64 accm[PRE_BB], accf[PRE_BB];
    u64 bm = pack2f(b_my[c0], b_my[c0 + 1]);
    u64 bf = pack2f(b_ff[c0], b_ff[c0 + 1]);
#pragma unroll
    for (int bb = 0; bb < PRE_BB; bb++) { accm[bb] = bm; accf[bb] = bf; }

    for (int k = 0; k < Hh; k++) {
        u64 wm = *(const u64*)&W_my[(size_t)k * NG + c0];
        u64 wf = *(const u64*)&W_ff[(size_t)k * NG + c0];
#pragma unroll
        for (int bb = 0; bb < PRE_BB; bb++) {
            u64 hh = dup2f(hsh[k * PRE_BB + bb]);
            fma2(accm[bb], hh, wm);
            fma2(accf[bb], hh, wf);
        }
    }
    // pair-packed store: idx = ((b>>1)*NG + col)*2 + (b&1)
#pragma unroll
    for (int bb = 0; bb < PRE_BB; bb++) {
        int b = b0 + bb;
        size_t base = ((size_t)(b >> 1) * NG) * 2 + (b & 1);
        float v0, v1;
        unpack2(accm[bb], v0, v1);
        g_encW_my[base + 2 * (size_t)c0] = v0;
        g_encW_my[base + 2 * (size_t)(c0 + 1)] = v1;
        unpack2(accf[bb], v0, v1);
        g_encW_ff[base + 2 * (size_t)c0] = v0;
        g_encW_ff[base + 2 * (size_t)(c0 + 1)] = v1;
    }
}

// ---------------------------------------------------------------------------
// One LSTM update for 28 rows with 256 threads.
// Thread (j = tid&127, g = tid>>7): gate cols {j,j+128,j+256,j+384},
// rows g*14..g*14+13 as 7 packed row-pairs. Triple-buffered U staging.
// ---------------------------------------------------------------------------
template <int NQ>
__device__ __forceinline__ void lstm_phase(
    const float* __restrict__ encW,   // pair-packed
    const float* __restrict__ Ug,
    const float* __restrict__ Wg,     // W matrix (tail rows H..H+NQ-1 used)
    const float* sh_cond, float* sh_h, float* sh_U,
    float (&c)[14], int j, int rbl, const int* epair, int tid)
{
    stage_chunk(sh_U,            Ug,                       tid);
    stage_chunk(sh_U + KCH * NG, Ug + (size_t)KCH * NG,    tid);

    // ---- acc init: encW (bias folded, LDG.64) + cond-tail @ W[H:, :] ----
    u64 acc[4][7];
#pragma unroll
    for (int g4 = 0; g4 < 4; g4++) {
        const int col = g4 * 128 + j;
#pragma unroll
        for (int p = 0; p < 7; p++)
            acc[g4][p] = *(const u64*)&encW[((size_t)epair[p] * NG + col) * 2];
    }
#pragma unroll
    for (int q = 0; q < NQ; q++) {
        u64 cpp[7];
#pragma unroll
        for (int p = 0; p < 7; p++)
            cpp[p] = *(const u64*)(sh_cond + q * HSTR + rbl + 2 * p);
#pragma unroll
        for (int g4 = 0; g4 < 4; g4++) {
            u64 wd = dup2f(__ldg(&Wg[(size_t)(Hh + q) * NG + g4 * 128 + j]));
#pragma unroll
            for (int p = 0; p < 7; p++) fma2(acc[g4][p], cpp[p], wd);
        }
    }

    // ---- main GEMM, one barrier per chunk ----
    for (int ch = 0; ch < NCHUNK; ch++) {
        if (ch == NCHUNK - 1) cp_wait<0>(); else cp_wait<1>();
        __syncthreads();   // chunk ch visible; all threads past compute(ch-1)
        if (ch + 2 < NCHUNK)
            stage_chunk(sh_U + ((ch + 2) % 3) * KCH * NG,
                        Ug + (size_t)(ch + 2) * KCH * NG, tid);
        const float* ub = sh_U + (ch % 3) * KCH * NG;
        const float* hb = sh_h + (ch * KCH) * HSTR + rbl;
#pragma unroll
        for (int kk = 0; kk < KCH; kk++) {
            const float* ur = ub + kk * NG + j;
            u64 u0 = dup2f(ur[0]);
            u64 u1 = dup2f(ur[128]);
            u64 u2 = dup2f(ur[256]);
            u64 u3 = dup2f(ur[384]);
            const u64* hp = (const u64*)(hb + kk * HSTR);
#pragma unroll
            for (int p = 0; p < 7; p++) {
                u64 h2 = hp[p];
                fma2(acc[0][p], h2, u0);
                fma2(acc[1][p], h2, u1);
                fma2(acc[2][p], h2, u2);
                fma2(acc[3][p], h2, u3);
            }
        }
    }
    __syncthreads();  // all threads done reading old sh_h

    // ---- gates; c register-private ----
#pragma unroll
    for (int p = 0; p < 7; p++) {
        float zi0, zi1, zf0, zf1, zg0, zg1, zo0, zo1;
        unpack2(acc[0][p], zi0, zi1);
        unpack2(acc[1][p], zf0, zf1);
        unpack2(acc[2][p], zg0, zg1);
        unpack2(acc[3][p], zo0, zo1);
        float c20 = sigf(zf0) * c[2 * p]     + sigf(zi0) * tanhf_fast(zg0);
        float c21 = sigf(zf1) * c[2 * p + 1] + sigf(zi1) * tanhf_fast(zg1);
        c[2 * p] = c20; c[2 * p + 1] = c21;
        *(u64*)(sh_h + j * HSTR + rbl + 2 * p) =
            pack2f(sigf(zo0) * tanhf_fast(c20), sigf(zo1) * tanhf_fast(c21));
    }
}

// ---------------------------------------------------------------------------
__global__ __launch_bounds__(NTHREADS, 2) void decoder_kernel(
    const float* __restrict__ cond_m, const float* __restrict__ cond_y,
    const float* __restrict__ cond_f, const float* __restrict__ cond_fa,
    const float* __restrict__ state_h, const float* __restrict__ state_c,
    const float* __restrict__ U_my, const float* __restrict__ U_ff,
    const float* __restrict__ W_my, const float* __restrict__ W_ff,
    const float* __restrict__ Wh_my, const float* __restrict__ bh_my,
    const float* __restrict__ Wh_ff, const float* __restrict__ bh_ff,
    const float* __restrict__ gumbel, const float* __restrict__ znorm,
    float* __restrict__ out)
{
    extern __shared__ float smem[];
    float* sh_U     = smem;                       // 3*KCH*NG = 12288 floats
    float* sh_h_my  = sh_U + 3 * KCH * NG;        // Hh*HSTR
    float* sh_h_ff  = sh_h_my + Hh * HSTR;
    float* sh_cond5 = sh_h_ff + Hh * HSTR;        // [q][HSTR]
    float* sh_cond2 = sh_cond5 + 5 * HSTR;
    float* sh_r     = sh_cond2 + 2 * HSTR;        // [row][76]

    const int tid = threadIdx.x;
    const int rowbase = blockIdx.x * ROWS;
    const int j = tid & 127;
    const int g = tid >> 7;        // 0..1
    const int rbl = g * 14;

    // ---- init h and cond ----
    for (int idx = tid; idx < Hh * ROWS; idx += NTHREADS) {
        int k = idx / ROWS, row = idx % ROWS;
        int b = min(rowbase + row, Bsz - 1);
        float hv = state_h[(size_t)b * Hh + k];
        sh_h_my[k * HSTR + row] = hv;
        sh_h_ff[k * HSTR + row] = hv;
    }
    if (tid < ROWS) {
        int row = tid;
        int b = min(rowbase + row, Bsz - 1);
        float m0 = cond_m[((size_t)b * Tt) * 2 + 0];
        float m1 = cond_m[((size_t)b * Tt) * 2 + 1];
        float y0 = cond_y[(size_t)b * Tt];
        float f0 = cond_f[(size_t)b * Tt];
        float a0 = cond_fa[(size_t)b * Tt];
        sh_cond5[0 * HSTR + row] = m0;
        sh_cond5[1 * HSTR + row] = m1;
        sh_cond5[2 * HSTR + row] = y0;
        sh_cond5[3 * HSTR + row] = f0;
        sh_cond5[4 * HSTR + row] = a0;
        sh_cond2[0 * HSTR + row] = f0;
        sh_cond2[1 * HSTR + row] = a0;
    }

    // ---- c state in registers, encW pair indices ----
    float cmy[14], cff[14];
    int epair[7];
#pragma unroll
    for (int r = 0; r < 14; r++) {
        int b = min(rowbase + rbl + r, Bsz - 1);
        float cv = state_c[(size_t)b * Hh + j];
        cmy[r] = cv; cff[r] = cv;
    }
#pragma unroll
    for (int p = 0; p < 7; p++)
        epair[p] = min(rowbase + rbl + 2 * p, Bsz - 2) >> 1;

    // head-phase mapping: 150 active threads, c=tid%75, half=tid/75
    const int hc = tid % 75;
    const int hhalf = tid / 75;
    const bool hact = tid < 150;

    float* out_gm  = out;
    float* out_gy  = out + (size_t)Bsz * Tt * 30;
    float* out_gf  = out + (size_t)Bsz * Tt * 45;
    float* out_gfa = out + (size_t)Bsz * Tt * 60;

    __syncthreads();

    for (int t = 0; t < Tt; t++) {
        lstm_phase<5>(g_encW_my, U_my, W_my, sh_cond5, sh_h_my, sh_U, cmy, j, rbl, epair, tid);
        lstm_phase<2>(g_encW_ff, U_ff, W_ff, sh_cond2, sh_h_ff, sh_U, cff, j, rbl, epair, tid);
        __syncthreads();  // h_my / h_ff visible

        // ===== heads: Wh from L1/L2, h pairs from smem =====
        if (hact) {
            const float* hb = ((hc < 45) ? sh_h_my : sh_h_ff) + hhalf * 14;
            const float* wsrc;
            int wstr;
            float bias;
            if (hc < 45) { wsrc = Wh_my + hc; wstr = 45; bias = bh_my[hc]; }
            else         { wsrc = Wh_ff + (hc - 45); wstr = 30; bias = bh_ff[hc - 45]; }
            u64 a[7];
            u64 binit = dup2f(bias);
#pragma unroll
            for (int p = 0; p < 7; p++) a[p] = binit;
#pragma unroll 4
            for (int k = 0; k < Hh; k++) {
                u64 wd = dup2f(__ldg(wsrc + (size_t)k * wstr));
                const u64* hp = (const u64*)(hb + k * HSTR);
#pragma unroll
                for (int p = 0; p < 7; p++) fma2(a[p], hp[p], wd);
            }
#pragma unroll
            for (int p = 0; p < 7; p++) {
                float v0, v1;
                unpack2(a[p], v0, v1);
                int row = hhalf * 14 + 2 * p;
                sh_r[row * 76 + hc] = v0;
                sh_r[(row + 1) * 76 + hc] = v1;
            }
        }
        __syncthreads();

        // ===== sampling / cond update / outputs =====
        if (tid < 4 * ROWS) {
            const int row = tid >> 2;
            const int d = tid & 3;
            const bool valid = (rowbase + row) < Bsz;
            const int b = min(rowbase + row, Bsz - 1);
            const int tn = min(t + 1, Tt - 1);
            const float* gum = gumbel + (((size_t)t * 4 + d) * Bsz + b) * KcK;
            const float* zn = znorm + ((size_t)t * Bsz + b) * 5;

            if (d == 0) {
                const float* rb = sh_r + row * 76;
                float lg[5], mul[5], sl[5], mulat[5], slat[5], rho[5];
#pragma unroll
                for (int k = 0; k < 5; k++) {
                    lg[k]    = rb[k];
                    mul[k]   = rb[5 + k];
                    sl[k]    = expf_fast(rb[10 + k]);
                    mulat[k] = rb[15 + k];
                    slat[k]  = expf_fast(rb[20 + k]);
                    rho[k]   = tanhf_fast(rb[25 + k]);
                }
                float mx = lg[0];
#pragma unroll
                for (int k = 1; k < 5; k++) mx = fmaxf(mx, lg[k]);
                float am[5], ssum = 0.0f;
#pragma unroll
                for (int k = 0; k < 5; k++) { am[k] = expf_fast(lg[k] - mx); ssum += am[k]; }
                float inv = 1.0f / ssum;
#pragma unroll
                for (int k = 0; k < 5; k++) am[k] *= inv;
                int im = 0; float best = lg[0] + gum[0];
#pragma unroll
                for (int k = 1; k < 5; k++) {
                    float v = lg[k] + gum[k];
                    if (v > best) { best = v; im = k; }
                }
                float z1 = zn[0], z2 = zn[1];
                float rr = rho[im];
                float s_long = mul[im] + sl[im] * z1;
                float s_lt = mulat[im] + slat[im] * (rr * z1 + sqrtf(fmaxf(1.0f - rr * rr, 0.0f)) * z2);
                float nm0 = cond_m[((size_t)b * Tt + tn) * 2 + 0];
                float nm1 = cond_m[((size_t)b * Tt + tn) * 2 + 1];
                sh_cond5[0 * HSTR + row] = (fabsf(s_long - nm0) < 0.3f) ? s_long : nm0;
                sh_cond5[1 * HSTR + row] = (fabsf(s_lt  - nm1) < 0.1f) ? s_lt  : nm1;
                if (valid) {
                    float* o = out_gm + ((size_t)b * Tt + t) * 30;
#pragma unroll
                    for (int k = 0; k < 5; k++) {
                        o[k] = am[k]; o[5 + k] = mul[k]; o[10 + k] = sl[k];
                        o[15 + k] = mulat[k]; o[20 + k] = slat[k]; o[25 + k] = rho[k];
                    }
                }
            } else {
                const float* rb;
                float zv, nv;
                float* osec;
                if (d == 1) {
                    rb = sh_r + row * 76 + 30; zv = zn[2];
                    nv = cond_y[(size_t)b * Tt + tn]; osec = out_gy;
                } else if (d == 2) {
                    rb = sh_r + row * 76 + 45; zv = zn[3];
                    nv = cond_f[(size_t)b * Tt + tn]; osec = out_gf;
                } else {
                    rb = sh_r + row * 76 + 60; zv = zn[4];
                    nv = cond_fa[(size_t)b * Tt + tn]; osec = out_gfa;
                }
                float lg[5], mu[5], s[5];
#pragma unroll
                for (int k = 0; k < 5; k++) {
                    lg[k] = rb[k]; mu[k] = rb[5 + k]; s[k] = expf_fast(rb[10 + k]);
                }
                float mx = lg[0];
#pragma unroll
                for (int k = 1; k < 5; k++) mx = fmaxf(mx, lg[k]);
                float am[5], ssum = 0.0f;
#pragma unroll
                for (int k = 0; k < 5; k++) { am[k] = expf_fast(lg[k] - mx); ssum += am[k]; }
                float inv = 1.0f / ssum;
#pragma unroll
                for (int k = 0; k < 5; k++) am[k] *= inv;
                int im = 0; float best = lg[0] + gum[0];
#pragma unroll
                for (int k = 1; k < 5; k++) {
                    float v = lg[k] + gum[k];
                    if (v > best) { best = v; im = k; }
                }
                float samp = mu[im] + s[im] * zv;
                float cn = (fabsf(samp - nv) < 0.3f) ? samp : nv;
                if (d == 1) {
                    sh_cond5[2 * HSTR + row] = cn;
                } else if (d == 2) {
                    sh_cond5[3 * HSTR + row] = cn;
                    sh_cond2[0 * HSTR + row] = cn;
                } else {
                    sh_cond5[4 * HSTR + row] = cn;
                    sh_cond2[1 * HSTR + row] = cn;
                }
                if (valid) {
                    float* o = osec + ((size_t)b * Tt + t) * 15;
#pragma unroll
                    for (int k = 0; k < 5; k++) {
                        o[k] = am[k]; o[5 + k] = mu[k]; o[10 + k] = s[k];
                    }
                }
            }
        }
        __syncthreads();  // cond updated for next step
    }
}

// ---------------------------------------------------------------------------
extern "C" void kernel_launch(void* const* d_in, const int* in_sizes, int n_in,
                              void* d_out, int out_size)
{
    (void)in_sizes; (void)n_in; (void)out_size;
    const float* cond_m  = (const float*)d_in[0];
    const float* cond_y  = (const float*)d_in[1];
    const float* cond_f  = (const float*)d_in[2];
    const float* cond_fa = (const float*)d_in[3];
    const float* state_h = (const float*)d_in[4];
    const float* state_c = (const float*)d_in[5];
    const float* W_my    = (const float*)d_in[6];
    const float* U_my    = (const float*)d_in[7];
    const float* b_my    = (const float*)d_in[8];
    const float* W_ff    = (const float*)d_in[9];
    const float* U_ff    = (const float*)d_in[10];
    const float* b_ff    = (const float*)d_in[11];
    const float* Wh_my   = (const float*)d_in[12];
    const float* bh_my   = (const float*)d_in[13];
    const float* Wh_ff   = (const float*)d_in[14];
    const float* bh_ff   = (const float*)d_in[15];
    const float* gumbel  = (const float*)d_in[16];
    const float* znorm   = (const float*)d_in[17];
    float* out = (float*)d_out;

    const int smem_floats = 3 * KCH * NG + 2 * Hh * HSTR + 7 * HSTR + ROWS * 76;
    const int smem_bytes = smem_floats * (int)sizeof(float);  // ~89.2 KB

    cudaFuncSetAttribute(decoder_kernel,
                         cudaFuncAttributeMaxDynamicSharedMemorySize, smem_bytes);

    precompute_kernel<<<Bsz / PRE_BB, 256>>>(state_h, W_my, b_my, W_ff, b_ff);
    decoder_kernel<<<NCTA, NTHREADS, smem_bytes>>>(
        cond_m, cond_y, cond_f, cond_fa, state_h, state_c,
        U_my, U_ff, W_my, W_ff, Wh_my, bh_my, Wh_ff, bh_ff,
        gumbel, znorm, out);
}

// round 4
// speedup vs baseline: 1.0197x; 1.0197x over previous
#include <cuda_runtime.h>
#include <cuda_bf16.h>

// ---------------------------------------------------------------------------
// Decoder_65111704207909  (B=8192, T=20, H=128, K=5)
// Round 4: 2 CTAs/SM x 256 thr, 28 rows/CTA, grid=293.
//  - U pre-transposed (gate-interleaved) -> ONE LDS.128 per k in GEMM loop
//  - Wh pre-transposed row-contiguous -> LDG.128, L1-resident across steps
//  - triple-buffered cp.async, one barrier per chunk; encW pair-packed
// ---------------------------------------------------------------------------

#define Bsz 8192
#define Tt 20
#define Hh 128
#define KcK 5
#define NG 512                    // 4*H
#define ROWS 28
#define NCTA 293
#define NTHREADS 256
#define HSTR 30                   // padded row stride (even)
#define KCH 8                     // k-rows per staged chunk
#define NCHUNK (Hh / KCH)         // 16
#define PRE_BB 16

typedef unsigned long long u64;

// enc_h @ W[:H] + b (bias folded), pair-packed: [(b>>1)][col][b&1]
__device__ float g_encW_my[(size_t)Bsz * NG];
__device__ float g_encW_ff[(size_t)Bsz * NG];
// U transposed: [k][j][g]  (g = gate 0..3, contiguous)
__device__ float g_Ut_my[(size_t)Hh * NG];
__device__ float g_Ut_ff[(size_t)Hh * NG];
// Wh transposed: [c][k], c<45 -> Wh_my col c ; 45<=c<75 -> Wh_ff col c-45
__device__ float g_Wht[75 * Hh];

__device__ __forceinline__ u64 pack2f(float x, float y) {
    u64 r; asm("mov.b64 %0, {%1, %2};" : "=l"(r) : "f"(x), "f"(y)); return r;
}
__device__ __forceinline__ u64 dup2f(float x) {
    u64 r; asm("mov.b64 %0, {%1, %1};" : "=l"(r) : "f"(x)); return r;
}
__device__ __forceinline__ void fma2(u64& d, u64 a, u64 b) {
    asm("fma.rn.f32x2 %0, %1, %2, %0;" : "+l"(d) : "l"(a), "l"(b));
}
__device__ __forceinline__ void unpack2(u64 v, float& x, float& y) {
    asm("mov.b64 {%0, %1}, %2;" : "=f"(x), "=f"(y) : "l"(v));
}

// ---- fast transcendentals ----
__device__ __forceinline__ float ex2f(float x) {
    float y; asm("ex2.approx.f32 %0, %1;" : "=f"(y) : "f"(x)); return y;
}
__device__ __forceinline__ float rcpf(float x) {
    float y; asm("rcp.approx.f32 %0, %1;" : "=f"(y) : "f"(x)); return y;
}
#define LOG2E 1.4426950408889634f
__device__ __forceinline__ float sigf(float x) {
    return rcpf(1.0f + ex2f(-LOG2E * x));
}
__device__ __forceinline__ float tanhf_fast(float x) {
    return fmaf(-2.0f, rcpf(1.0f + ex2f((2.0f * LOG2E) * x)), 1.0f);
}
__device__ __forceinline__ float expf_fast(float x) { return ex2f(LOG2E * x); }

// ---- cp.async: one chunk = KCH*NG floats = 16KB = 256 thr x 4 x 16B ----
__device__ __forceinline__ void stage_chunk(float* dst, const float* __restrict__ src, int tid) {
    unsigned smp = (unsigned)__cvta_generic_to_shared(dst);
#pragma unroll
    for (int i = 0; i < 4; i++) {
        asm volatile("cp.async.cg.shared.global [%0], [%1], 16;"
                     :: "r"(smp + (unsigned)((tid + i * NTHREADS) * 16)),
                        "l"(src + (size_t)(tid + i * NTHREADS) * 4)
                     : "memory");
    }
    asm volatile("cp.async.commit_group;" ::: "memory");
}
template <int N>
__device__ __forceinline__ void cp_wait() {
    asm volatile("cp.async.wait_group %0;" :: "n"(N) : "memory");
}

// ---------------------------------------------------------------------------
// One-time transposes (per replay): U -> gate-interleaved, Wh -> row-major.
// ---------------------------------------------------------------------------
__global__ __launch_bounds__(256) void transpose_kernel(
    const float* __restrict__ U_my, const float* __restrict__ U_ff,
    const float* __restrict__ Wh_my, const float* __restrict__ Wh_ff)
{
    int tid = blockIdx.x * 256 + threadIdx.x;
    if (tid < Hh * NG) {
        int k = tid >> 9;
        int r = tid & 511;
        int j = r >> 2, g = r & 3;
        g_Ut_my[tid] = U_my[(size_t)k * NG + g * 128 + j];
        g_Ut_ff[tid] = U_ff[(size_t)k * NG + g * 128 + j];
    }
    if (tid < 75 * Hh) {
        int c = tid >> 7, k = tid & 127;
        g_Wht[tid] = (c < 45) ? Wh_my[(size_t)k * 45 + c]
                              : Wh_ff[(size_t)k * 30 + (c - 45)];
    }
}

// ---------------------------------------------------------------------------
// Precompute: g_encW = state_h @ W[:H, :] + b (both LSTMs), pair-packed layout
// ---------------------------------------------------------------------------
__global__ __launch_bounds__(256) void precompute_kernel(
    const float* __restrict__ state_h,
    const float* __restrict__ W_my, const float* __restrict__ b_my,
    const float* __restrict__ W_ff, const float* __restrict__ b_ff)
{
    __shared__ float hsh[Hh * PRE_BB];  // [k][bb]
    const int t = threadIdx.x;
    const int b0 = blockIdx.x * PRE_BB;

    for (int idx = t; idx < Hh * PRE_BB; idx += 256) {
        int k = idx / PRE_BB, bb = idx % PRE_BB;
        hsh[idx] = state_h[(size_t)(b0 + bb) * Hh + k];
    }
    __syncthreads();

    const int c0 = 2 * t;
    u64 accm[PRE_BB], accf[PRE_BB];
    u64 bm = pack2f(b_my[c0], b_my[c0 + 1]);
    u64 bf = pack2f(b_ff[c0], b_ff[c0 + 1]);
#pragma unroll
    for (int bb = 0; bb < PRE_BB; bb++) { accm[bb] = bm; accf[bb] = bf; }

    for (int k = 0; k < Hh; k++) {
        u64 wm = *(const u64*)&W_my[(size_t)k * NG + c0];
        u64 wf = *(const u64*)&W_ff[(size_t)k * NG + c0];
#pragma unroll
        for (int bb = 0; bb < PRE_BB; bb++) {
            u64 hh = dup2f(hsh[k * PRE_BB + bb]);
            fma2(accm[bb], hh, wm);
            fma2(accf[bb], hh, wf);
        }
    }
    // pair-packed store: idx = ((b>>1)*NG + col)*2 + (b&1)
#pragma unroll
    for (int bb = 0; bb < PRE_BB; bb++) {
        int b = b0 + bb;
        size_t base = ((size_t)(b >> 1) * NG) * 2 + (b & 1);
        float v0, v1;
        unpack2(accm[bb], v0, v1);
        g_encW_my[base + 2 * (size_t)c0] = v0;
        g_encW_my[base + 2 * (size_t)(c0 + 1)] = v1;
        unpack2(accf[bb], v0, v1);
        g_encW_ff[base + 2 * (size_t)c0] = v0;
        g_encW_ff[base + 2 * (size_t)(c0 + 1)] = v1;
    }
}

// ---------------------------------------------------------------------------
// One LSTM update for 28 rows with 256 threads.
// Thread (j = tid&127, g = tid>>7): gate cols {j,j+128,j+256,j+384},
// rows g*14..g*14+13 as 7 packed row-pairs. U from transposed layout:
// one LDS.128 yields all 4 gate weights for column j at row k.
// ---------------------------------------------------------------------------
template <int NQ>
__device__ __forceinline__ void lstm_phase(
    const float* __restrict__ encW,   // pair-packed
    const float* __restrict__ Ut,     // gate-interleaved [k][j][g]
    const float* __restrict__ Wg,     // W matrix (tail rows H.. used)
    const float* sh_cond, float* sh_h, float* sh_U,
    float (&c)[14], int j, int rbl, const int* epair, int tid)
{
    stage_chunk(sh_U,            Ut,                    tid);
    stage_chunk(sh_U + KCH * NG, Ut + (size_t)KCH * NG, tid);

    // ---- acc init: encW (bias folded, LDG.64) + cond-tail @ W[H:, :] ----
    u64 acc[4][7];
#pragma unroll
    for (int g4 = 0; g4 < 4; g4++) {
        const int col = g4 * 128 + j;
#pragma unroll
        for (int p = 0; p < 7; p++)
            acc[g4][p] = *(const u64*)&encW[((size_t)epair[p] * NG + col) * 2];
    }
#pragma unroll
    for (int q = 0; q < NQ; q++) {
        u64 cpp[7];
#pragma unroll
        for (int p = 0; p < 7; p++)
            cpp[p] = *(const u64*)(sh_cond + q * HSTR + rbl + 2 * p);
#pragma unroll
        for (int g4 = 0; g4 < 4; g4++) {
            u64 wd = dup2f(__ldg(&Wg[(size_t)(Hh + q) * NG + g4 * 128 + j]));
#pragma unroll
            for (int p = 0; p < 7; p++) fma2(acc[g4][p], cpp[p], wd);
        }
    }

    // ---- main GEMM, one barrier per chunk ----
    for (int ch = 0; ch < NCHUNK; ch++) {
        if (ch == NCHUNK - 1) cp_wait<0>(); else cp_wait<1>();
        __syncthreads();   // chunk ch visible; all past compute(ch-1)
        if (ch + 2 < NCHUNK)
            stage_chunk(sh_U + ((ch + 2) % 3) * KCH * NG,
                        Ut + (size_t)(ch + 2) * KCH * NG, tid);
        const float* ub = sh_U + (ch % 3) * KCH * NG + 4 * j;
        const float* hb = sh_h + (ch * KCH) * HSTR + rbl;
#pragma unroll
        for (int kk = 0; kk < KCH; kk++) {
            float4 uu = *(const float4*)(ub + kk * NG);
            u64 u0 = dup2f(uu.x);
            u64 u1 = dup2f(uu.y);
            u64 u2 = dup2f(uu.z);
            u64 u3 = dup2f(uu.w);
            const u64* hp = (const u64*)(hb + kk * HSTR);
#pragma unroll
            for (int p = 0; p < 7; p++) {
                u64 h2 = hp[p];
                fma2(acc[0][p], h2, u0);
                fma2(acc[1][p], h2, u1);
                fma2(acc[2][p], h2, u2);
                fma2(acc[3][p], h2, u3);
            }
        }
    }
    __syncthreads();  // all threads done reading old sh_h

    // ---- gates; c register-private ----
#pragma unroll
    for (int p = 0; p < 7; p++) {
        float zi0, zi1, zf0, zf1, zg0, zg1, zo0, zo1;
        unpack2(acc[0][p], zi0, zi1);
        unpack2(acc[1][p], zf0, zf1);
        unpack2(acc[2][p], zg0, zg1);
        unpack2(acc[3][p], zo0, zo1);
        float c20 = sigf(zf0) * c[2 * p]     + sigf(zi0) * tanhf_fast(zg0);
        float c21 = sigf(zf1) * c[2 * p + 1] + sigf(zi1) * tanhf_fast(zg1);
        c[2 * p] = c20; c[2 * p + 1] = c21;
        *(u64*)(sh_h + j * HSTR + rbl + 2 * p) =
            pack2f(sigf(zo0) * tanhf_fast(c20), sigf(zo1) * tanhf_fast(c21));
    }
}

// ---------------------------------------------------------------------------
__global__ __launch_bounds__(NTHREADS, 2) void decoder_kernel(
    const float* __restrict__ cond_m, const float* __restrict__ cond_y,
    const float* __restrict__ cond_f, const float* __restrict__ cond_fa,
    const float* __restrict__ state_h, const float* __restrict__ state_c,
    const float* __restrict__ W_my, const float* __restrict__ W_ff,
    const float* __restrict__ bh_my, const float* __restrict__ bh_ff,
    const float* __restrict__ gumbel, const float* __restrict__ znorm,
    float* __restrict__ out)
{
    extern __shared__ float smem[];
    float* sh_U     = smem;                       // 3*KCH*NG = 12288 floats
    float* sh_h_my  = sh_U + 3 * KCH * NG;        // Hh*HSTR
    float* sh_h_ff  = sh_h_my + Hh * HSTR;
    float* sh_cond5 = sh_h_ff + Hh * HSTR;        // [q][HSTR]
    float* sh_cond2 = sh_cond5 + 5 * HSTR;
    float* sh_r     = sh_cond2 + 2 * HSTR;        // [row][76]

    const int tid = threadIdx.x;
    const int rowbase = blockIdx.x * ROWS;
    const int j = tid & 127;
    const int g = tid >> 7;        // 0..1
    const int rbl = g * 14;

    // ---- init h and cond ----
    for (int idx = tid; idx < Hh * ROWS; idx += NTHREADS) {
        int k = idx / ROWS, row = idx % ROWS;
        int b = min(rowbase + row, Bsz - 1);
        float hv = state_h[(size_t)b * Hh + k];
        sh_h_my[k * HSTR + row] = hv;
        sh_h_ff[k * HSTR + row] = hv;
    }
    if (tid < ROWS) {
        int row = tid;
        int b = min(rowbase + row, Bsz - 1);
        float m0 = cond_m[((size_t)b * Tt) * 2 + 0];
        float m1 = cond_m[((size_t)b * Tt) * 2 + 1];
        float y0 = cond_y[(size_t)b * Tt];
        float f0 = cond_f[(size_t)b * Tt];
        float a0 = cond_fa[(size_t)b * Tt];
        sh_cond5[0 * HSTR + row] = m0;
        sh_cond5[1 * HSTR + row] = m1;
        sh_cond5[2 * HSTR + row] = y0;
        sh_cond5[3 * HSTR + row] = f0;
        sh_cond5[4 * HSTR + row] = a0;
        sh_cond2[0 * HSTR + row] = f0;
        sh_cond2[1 * HSTR + row] = a0;
    }

    // ---- c state in registers, encW pair indices ----
    float cmy[14], cff[14];
    int epair[7];
#pragma unroll
    for (int r = 0; r < 14; r++) {
        int b = min(rowbase + rbl + r, Bsz - 1);
        float cv = state_c[(size_t)b * Hh + j];
        cmy[r] = cv; cff[r] = cv;
    }
#pragma unroll
    for (int p = 0; p < 7; p++)
        epair[p] = min(rowbase + rbl + 2 * p, Bsz - 2) >> 1;

    // head-phase mapping: 150 active threads, c=tid%75, half=tid/75
    const int hc = tid % 75;
    const int hhalf = tid / 75;
    const bool hact = tid < 150;
    float hbias = 0.0f;
    if (hact) hbias = (hc < 45) ? bh_my[hc] : bh_ff[hc - 45];

    float* out_gm  = out;
    float* out_gy  = out + (size_t)Bsz * Tt * 30;
    float* out_gf  = out + (size_t)Bsz * Tt * 45;
    float* out_gfa = out + (size_t)Bsz * Tt * 60;

    __syncthreads();

    for (int t = 0; t < Tt; t++) {
        lstm_phase<5>(g_encW_my, g_Ut_my, W_my, sh_cond5, sh_h_my, sh_U, cmy, j, rbl, epair, tid);
        lstm_phase<2>(g_encW_ff, g_Ut_ff, W_ff, sh_cond2, sh_h_ff, sh_U, cff, j, rbl, epair, tid);
        __syncthreads();  // h_my / h_ff visible

        // ===== heads: Wht row-contiguous LDG.128, h pairs from smem =====
        if (hact) {
            const float* hb = ((hc < 45) ? sh_h_my : sh_h_ff) + hhalf * 14;
            const float4* wr = (const float4*)(g_Wht + hc * Hh);
            u64 a[7];
            u64 binit = dup2f(hbias);
#pragma unroll
            for (int p = 0; p < 7; p++) a[p] = binit;
#pragma unroll 8
            for (int k4 = 0; k4 < Hh / 4; k4++) {
                float4 w4 = __ldg(&wr[k4]);
                const float* hk = hb + (4 * k4) * HSTR;
                u64 w0 = dup2f(w4.x);
                u64 w1 = dup2f(w4.y);
                u64 w2 = dup2f(w4.z);
                u64 w3 = dup2f(w4.w);
#pragma unroll
                for (int p = 0; p < 7; p++) {
                    fma2(a[p], *(const u64*)(hk + 2 * p), w0);
                    fma2(a[p], *(const u64*)(hk + HSTR + 2 * p), w1);
                    fma2(a[p], *(const u64*)(hk + 2 * HSTR + 2 * p), w2);
                    fma2(a[p], *(const u64*)(hk + 3 * HSTR + 2 * p), w3);
                }
            }
#pragma unroll
            for (int p = 0; p < 7; p++) {
                float v0, v1;
                unpack2(a[p], v0, v1);
                int row = hhalf * 14 + 2 * p;
                sh_r[row * 76 + hc] = v0;
                sh_r[(row + 1) * 76 + hc] = v1;
            }
        }
        __syncthreads();

        // ===== sampling / cond update / outputs =====
        if (tid < 4 * ROWS) {
            const int row = tid >> 2;
            const int d = tid & 3;
            const bool valid = (rowbase + row) < Bsz;
            const int b = min(rowbase + row, Bsz - 1);
            const int tn = min(t + 1, Tt - 1);
            const float* gum = gumbel + (((size_t)t * 4 + d) * Bsz + b) * KcK;
            const float* zn = znorm + ((size_t)t * Bsz + b) * 5;

            if (d == 0) {
                const float* rb = sh_r + row * 76;
                float lg[5], mul[5], sl[5], mulat[5], slat[5], rho[5];
#pragma unroll
                for (int k = 0; k < 5; k++) {
                    lg[k]    = rb[k];
                    mul[k]   = rb[5 + k];
                    sl[k]    = expf_fast(rb[10 + k]);
                    mulat[k] = rb[15 + k];
                    slat[k]  = expf_fast(rb[20 + k]);
                    rho[k]   = tanhf_fast(rb[25 + k]);
                }
                float mx = lg[0];
#pragma unroll
                for (int k = 1; k < 5; k++) mx = fmaxf(mx, lg[k]);
                float am[5], ssum = 0.0f;
#pragma unroll
                for (int k = 0; k < 5; k++) { am[k] = expf_fast(lg[k] - mx); ssum += am[k]; }
                float inv = 1.0f / ssum;
#pragma unroll
                for (int k = 0; k < 5; k++) am[k] *= inv;
                int im = 0; float best = lg[0] + gum[0];
#pragma unroll
                for (int k = 1; k < 5; k++) {
                    float v = lg[k] + gum[k];
                    if (v > best) { best = v; im = k; }
                }
                float z1 = zn[0], z2 = zn[1];
                float rr = rho[im];
                float s_long = mul[im] + sl[im] * z1;
                float s_lt = mulat[im] + slat[im] * (rr * z1 + sqrtf(fmaxf(1.0f - rr * rr, 0.0f)) * z2);
                float nm0 = cond_m[((size_t)b * Tt + tn) * 2 + 0];
                float nm1 = cond_m[((size_t)b * Tt + tn) * 2 + 1];
                sh_cond5[0 * HSTR + row] = (fabsf(s_long - nm0) < 0.3f) ? s_long : nm0;
                sh_cond5[1 * HSTR + row] = (fabsf(s_lt  - nm1) < 0.1f) ? s_lt  : nm1;
                if (valid) {
                    float* o = out_gm + ((size_t)b * Tt + t) * 30;
#pragma unroll
                    for (int k = 0; k < 5; k++) {
                        o[k] = am[k]; o[5 + k] = mul[k]; o[10 + k] = sl[k];
                        o[15 + k] = mulat[k]; o[20 + k] = slat[k]; o[25 + k] = rho[k];
                    }
                }
            } else {
                const float* rb;
                float zv, nv;
                float* osec;
                if (d == 1) {
                    rb = sh_r + row * 76 + 30; zv = zn[2];
                    nv = cond_y[(size_t)b * Tt + tn]; osec = out_gy;
                } else if (d == 2) {
                    rb = sh_r + row * 76 + 45; zv = zn[3];
                    nv = cond_f[(size_t)b * Tt + tn]; osec = out_gf;
                } else {
                    rb = sh_r + row * 76 + 60; zv = zn[4];
                    nv = cond_fa[(size_t)b * Tt + tn]; osec = out_gfa;
                }
                float lg[5], mu[5], s[5];
#pragma unroll
                for (int k = 0; k < 5; k++) {
                    lg[k] = rb[k]; mu[k] = rb[5 + k]; s[k] = expf_fast(rb[10 + k]);
                }
                float mx = lg[0];
#pragma unroll
                for (int k = 1; k < 5; k++) mx = fmaxf(mx, lg[k]);
                float am[5], ssum = 0.0f;
#pragma unroll
                for (int k = 0; k < 5; k++) { am[k] = expf_fast(lg[k] - mx); ssum += am[k]; }
                float inv = 1.0f / ssum;
#pragma unroll
                for (int k = 0; k < 5; k++) am[k] *= inv;
                int im = 0; float best = lg[0] + gum[0];
#pragma unroll
                for (int k = 1; k < 5; k++) {
                    float v = lg[k] + gum[k];
                    if (v > best) { best = v; im = k; }
                }
                float samp = mu[im] + s[im] * zv;
                float cn = (fabsf(samp - nv) < 0.3f) ? samp : nv;
                if (d == 1) {
                    sh_cond5[2 * HSTR + row] = cn;
                } else if (d == 2) {
                    sh_cond5[3 * HSTR + row] = cn;
                    sh_cond2[0 * HSTR + row] = cn;
                } else {
                    sh_cond5[4 * HSTR + row] = cn;
                    sh_cond2[1 * HSTR + row] = cn;
                }
                if (valid) {
                    float* o = osec + ((size_t)b * Tt + t) * 15;
#pragma unroll
                    for (int k = 0; k < 5; k++) {
                        o[k] = am[k]; o[5 + k] = mu[k]; o[10 + k] = s[k];
                    }
                }
            }
        }
        __syncthreads();  // cond updated for next step
    }
}

// ---------------------------------------------------------------------------
extern "C" void kernel_launch(void* const* d_in, const int* in_sizes, int n_in,
                              void* d_out, int out_size)
{
    (void)in_sizes; (void)n_in; (void)out_size;
    const float* cond_m  = (const float*)d_in[0];
    const float* cond_y  = (const float*)d_in[1];
    const float* cond_f  = (const float*)d_in[2];
    const float* cond_fa = (const float*)d_in[3];
    const float* state_h = (const float*)d_in[4];
    const float* state_c = (const float*)d_in[5];
    const float* W_my    = (const float*)d_in[6];
    const float* U_my    = (const float*)d_in[7];
    const float* b_my    = (const float*)d_in[8];
    const float* W_ff    = (const float*)d_in[9];
    const float* U_ff    = (const float*)d_in[10];
    const float* b_ff    = (const float*)d_in[11];
    const float* Wh_my   = (const float*)d_in[12];
    const float* bh_my   = (const float*)d_in[13];
    const float* Wh_ff   = (const float*)d_in[14];
    const float* bh_ff   = (const float*)d_in[15];
    const float* gumbel  = (const float*)d_in[16];
    const float* znorm   = (const float*)d_in[17];
    float* out = (float*)d_out;

    const int smem_floats = 3 * KCH * NG + 2 * Hh * HSTR + 7 * HSTR + ROWS * 76;
    const int smem_bytes = smem_floats * (int)sizeof(float);  // ~89.2 KB

    cudaFuncSetAttribute(decoder_kernel,
                         cudaFuncAttributeMaxDynamicSharedMemorySize, smem_bytes);

    transpose_kernel<<<(Hh * NG + 255) / 256, 256>>>(U_my, U_ff, Wh_my, Wh_ff);
    precompute_kernel<<<Bsz / PRE_BB, 256>>>(state_h, W_my, b_my, W_ff, b_ff);
    decoder_kernel<<<NCTA, NTHREADS, smem_bytes>>>(
        cond_m, cond_y, cond_f, cond_fa, state_h, state_c,
        W_my, W_ff, bh_my, bh_ff, gumbel, znorm, out);
}

// round 5
// speedup vs baseline: 1.0250x; 1.0051x over previous
#include <cuda_runtime.h>
#include <cuda_bf16.h>

// ---------------------------------------------------------------------------
// Decoder_65111704207909  (B=8192, T=20, H=128, K=5)
// Round 5: 2 CTAs/SM x 256 thr, 28 rows/CTA, grid=293.
//  - PHASE PARITY: odd CTAs run (ff,my), even (my,ff) -> co-resident CTAs
//    overlap MUFU/gate/sampling phases with each other's FFMA2 GEMM phases
//  - KCH=16 double-buffered cp.async: 9 barriers/phase instead of 17
//  - U gate-interleaved (LDS.128), Wh transposed (LDG.128), encW pair-packed
// ---------------------------------------------------------------------------

#define Bsz 8192
#define Tt 20
#define Hh 128
#define KcK 5
#define NG 512                    // 4*H
#define ROWS 28
#define NCTA 293
#define NTHREADS 256
#define HSTR 30                   // padded row stride (even)
#define KCH 16                    // k-rows per staged chunk
#define NCHUNK (Hh / KCH)         // 8
#define PRE_BB 16

typedef unsigned long long u64;

// enc_h @ W[:H] + b (bias folded), pair-packed: [(b>>1)][col][b&1]
__device__ float g_encW_my[(size_t)Bsz * NG];
__device__ float g_encW_ff[(size_t)Bsz * NG];
// U transposed: [k][j][g]  (g = gate 0..3, contiguous)
__device__ float g_Ut_my[(size_t)Hh * NG];
__device__ float g_Ut_ff[(size_t)Hh * NG];
// Wh transposed: [c][k]
__device__ float g_Wht[75 * Hh];

__device__ __forceinline__ u64 pack2f(float x, float y) {
    u64 r; asm("mov.b64 %0, {%1, %2};" : "=l"(r) : "f"(x), "f"(y)); return r;
}
__device__ __forceinline__ u64 dup2f(float x) {
    u64 r; asm("mov.b64 %0, {%1, %1};" : "=l"(r) : "f"(x)); return r;
}
__device__ __forceinline__ void fma2(u64& d, u64 a, u64 b) {
    asm("fma.rn.f32x2 %0, %1, %2, %0;" : "+l"(d) : "l"(a), "l"(b));
}
__device__ __forceinline__ void unpack2(u64 v, float& x, float& y) {
    asm("mov.b64 {%0, %1}, %2;" : "=f"(x), "=f"(y) : "l"(v));
}

// ---- fast transcendentals ----
__device__ __forceinline__ float ex2f(float x) {
    float y; asm("ex2.approx.f32 %0, %1;" : "=f"(y) : "f"(x)); return y;
}
__device__ __forceinline__ float rcpf(float x) {
    float y; asm("rcp.approx.f32 %0, %1;" : "=f"(y) : "f"(x)); return y;
}
#define LOG2E 1.4426950408889634f
__device__ __forceinline__ float sigf(float x) {
    return rcpf(1.0f + ex2f(-LOG2E * x));
}
__device__ __forceinline__ float tanhf_fast(float x) {
    return fmaf(-2.0f, rcpf(1.0f + ex2f((2.0f * LOG2E) * x)), 1.0f);
}
__device__ __forceinline__ float expf_fast(float x) { return ex2f(LOG2E * x); }

// ---- cp.async: one chunk = KCH*NG floats = 32KB = 256 thr x 8 x 16B ----
__device__ __forceinline__ void stage_chunk(float* dst, const float* __restrict__ src, int tid) {
    unsigned smp = (unsigned)__cvta_generic_to_shared(dst);
#pragma unroll
    for (int i = 0; i < 8; i++) {
        asm volatile("cp.async.cg.shared.global [%0], [%1], 16;"
                     :: "r"(smp + (unsigned)((tid + i * NTHREADS) * 16)),
                        "l"(src + (size_t)(tid + i * NTHREADS) * 4)
                     : "memory");
    }
    asm volatile("cp.async.commit_group;" ::: "memory");
}
template <int N>
__device__ __forceinline__ void cp_wait() {
    asm volatile("cp.async.wait_group %0;" :: "n"(N) : "memory");
}

// ---------------------------------------------------------------------------
// Precompute: g_encW = state_h @ W[:H,:] + b (pair-packed) AND the one-time
// transposes (U gate-interleaved, Wh row-major) folded into blocks 0..255.
// ---------------------------------------------------------------------------
__global__ __launch_bounds__(256) void precompute_kernel(
    const float* __restrict__ state_h,
    const float* __restrict__ W_my, const float* __restrict__ b_my,
    const float* __restrict__ W_ff, const float* __restrict__ b_ff,
    const float* __restrict__ U_my, const float* __restrict__ U_ff,
    const float* __restrict__ Wh_my, const float* __restrict__ Wh_ff)
{
    const int t = threadIdx.x;

    // ---- folded transposes (blocks 0..255 cover Hh*NG = 65536 elems) ----
    {
        int gidx = blockIdx.x * 256 + t;
        if (gidx < Hh * NG) {
            int k = gidx >> 9;
            int r = gidx & 511;
            int j = r >> 2, g = r & 3;
            g_Ut_my[gidx] = U_my[(size_t)k * NG + g * 128 + j];
            g_Ut_ff[gidx] = U_ff[(size_t)k * NG + g * 128 + j];
        }
        if (gidx < 75 * Hh) {
            int c = gidx >> 7, k = gidx & 127;
            g_Wht[gidx] = (c < 45) ? Wh_my[(size_t)k * 45 + c]
                                   : Wh_ff[(size_t)k * 30 + (c - 45)];
        }
    }

    __shared__ float hsh[Hh * PRE_BB];  // [k][bb]
    const int b0 = blockIdx.x * PRE_BB;

    for (int idx = t; idx < Hh * PRE_BB; idx += 256) {
        int k = idx / PRE_BB, bb = idx % PRE_BB;
        hsh[idx] = state_h[(size_t)(b0 + bb) * Hh + k];
    }
    __syncthreads();

    const int c0 = 2 * t;
    u64 accm[PRE_BB], accf[PRE_BB];
    u64 bm = pack2f(b_my[c0], b_my[c0 + 1]);
    u64 bf = pack2f(b_ff[c0], b_ff[c0 + 1]);
#pragma unroll
    for (int bb = 0; bb < PRE_BB; bb++) { accm[bb] = bm; accf[bb] = bf; }

    for (int k = 0; k < Hh; k++) {
        u64 wm = *(const u64*)&W_my[(size_t)k * NG + c0];
        u64 wf = *(const u64*)&W_ff[(size_t)k * NG + c0];
#pragma unroll
        for (int bb = 0; bb < PRE_BB; bb++) {
            u64 hh = dup2f(hsh[k * PRE_BB + bb]);
            fma2(accm[bb], hh, wm);
            fma2(accf[bb], hh, wf);
        }
    }
    // pair-packed store: idx = ((b>>1)*NG + col)*2 + (b&1)
#pragma unroll
    for (int bb = 0; bb < PRE_BB; bb++) {
        int b = b0 + bb;
        size_t base = ((size_t)(b >> 1) * NG) * 2 + (b & 1);
        float v0, v1;
        unpack2(accm[bb], v0, v1);
        g_encW_my[base + 2 * (size_t)c0] = v0;
        g_encW_my[base + 2 * (size_t)(c0 + 1)] = v1;
        unpack2(accf[bb], v0, v1);
        g_encW_ff[base + 2 * (size_t)c0] = v0;
        g_encW_ff[base + 2 * (size_t)(c0 + 1)] = v1;
    }
}

// ---------------------------------------------------------------------------
// One LSTM update for 28 rows with 256 threads.
// Thread (j = tid&127, g = tid>>7): gate cols {j,j+128,j+256,j+384},
// rows g*14..g*14+13 as 7 packed row-pairs. Double-buffered KCH=16 staging:
//   stage(0); for ch: { wait0; bar; stage(ch+1); compute(ch); }
// ---------------------------------------------------------------------------
template <int NQ>
__device__ __forceinline__ void lstm_phase(
    const float* __restrict__ encW,   // pair-packed
    const float* __restrict__ Ut,     // gate-interleaved [k][j][g]
    const float* __restrict__ Wg,     // W matrix (tail rows H.. used)
    const float* sh_cond, float* sh_h, float* sh_U,
    float (&c)[14], int j, int rbl, const int* epair, int tid)
{
    stage_chunk(sh_U, Ut, tid);

    // ---- acc init: encW (bias folded, LDG.64) + cond-tail @ W[H:, :] ----
    u64 acc[4][7];
#pragma unroll
    for (int g4 = 0; g4 < 4; g4++) {
        const int col = g4 * 128 + j;
#pragma unroll
        for (int p = 0; p < 7; p++)
            acc[g4][p] = *(const u64*)&encW[((size_t)epair[p] * NG + col) * 2];
    }
#pragma unroll
    for (int q = 0; q < NQ; q++) {
        u64 cpp[7];
#pragma unroll
        for (int p = 0; p < 7; p++)
            cpp[p] = *(const u64*)(sh_cond + q * HSTR + rbl + 2 * p);
#pragma unroll
        for (int g4 = 0; g4 < 4; g4++) {
            u64 wd = dup2f(__ldg(&Wg[(size_t)(Hh + q) * NG + g4 * 128 + j]));
#pragma unroll
            for (int p = 0; p < 7; p++) fma2(acc[g4][p], cpp[p], wd);
        }
    }

    // ---- main GEMM, double buffer, one barrier per chunk ----
    for (int ch = 0; ch < NCHUNK; ch++) {
        cp_wait<0>();
        __syncthreads();   // chunk ch visible; all warps past compute(ch-1)
        if (ch + 1 < NCHUNK)
            stage_chunk(sh_U + ((ch + 1) & 1) * KCH * NG,
                        Ut + (size_t)(ch + 1) * KCH * NG, tid);
        const float* ub = sh_U + (ch & 1) * KCH * NG + 4 * j;
        const float* hb = sh_h + (ch * KCH) * HSTR + rbl;
#pragma unroll
        for (int kk = 0; kk < KCH; kk++) {
            float4 uu = *(const float4*)(ub + kk * NG);
            u64 u0 = dup2f(uu.x);
            u64 u1 = dup2f(uu.y);
            u64 u2 = dup2f(uu.z);
            u64 u3 = dup2f(uu.w);
            const u64* hp = (const u64*)(hb + kk * HSTR);
#pragma unroll
            for (int p = 0; p < 7; p++) {
                u64 h2 = hp[p];
                fma2(acc[0][p], h2, u0);
                fma2(acc[1][p], h2, u1);
                fma2(acc[2][p], h2, u2);
                fma2(acc[3][p], h2, u3);
            }
        }
    }
    __syncthreads();  // all threads done reading old sh_h

    // ---- gates; c register-private ----
#pragma unroll
    for (int p = 0; p < 7; p++) {
        float zi0, zi1, zf0, zf1, zg0, zg1, zo0, zo1;
        unpack2(acc[0][p], zi0, zi1);
        unpack2(acc[1][p], zf0, zf1);
        unpack2(acc[2][p], zg0, zg1);
        unpack2(acc[3][p], zo0, zo1);
        float c20 = sigf(zf0) * c[2 * p]     + sigf(zi0) * tanhf_fast(zg0);
        float c21 = sigf(zf1) * c[2 * p + 1] + sigf(zi1) * tanhf_fast(zg1);
        c[2 * p] = c20; c[2 * p + 1] = c21;
        *(u64*)(sh_h + j * HSTR + rbl + 2 * p) =
            pack2f(sigf(zo0) * tanhf_fast(c20), sigf(zo1) * tanhf_fast(c21));
    }
}

// ---------------------------------------------------------------------------
__global__ __launch_bounds__(NTHREADS, 2) void decoder_kernel(
    const float* __restrict__ cond_m, const float* __restrict__ cond_y,
    const float* __restrict__ cond_f, const float* __restrict__ cond_fa,
    const float* __restrict__ state_h, const float* __restrict__ state_c,
    const float* __restrict__ W_my, const float* __restrict__ W_ff,
    const float* __restrict__ bh_my, const float* __restrict__ bh_ff,
    const float* __restrict__ gumbel, const float* __restrict__ znorm,
    float* __restrict__ out)
{
    extern __shared__ float smem[];
    float* sh_U     = smem;                       // 2*KCH*NG = 16384 floats
    float* sh_h_my  = sh_U + 2 * KCH * NG;        // Hh*HSTR
    float* sh_h_ff  = sh_h_my + Hh * HSTR;
    float* sh_cond5 = sh_h_ff + Hh * HSTR;        // [q][HSTR]
    float* sh_cond2 = sh_cond5 + 5 * HSTR;
    float* sh_r     = sh_cond2 + 2 * HSTR;        // [row][76]

    const int tid = threadIdx.x;
    const int rowbase = blockIdx.x * ROWS;
    const bool swap = (blockIdx.x & 1);   // phase-parity: odd CTAs do ff first
    const int j = tid & 127;
    const int g = tid >> 7;        // 0..1
    const int rbl = g * 14;

    // ---- init h and cond ----
    for (int idx = tid; idx < Hh * ROWS; idx += NTHREADS) {
        int k = idx / ROWS, row = idx % ROWS;
        int b = min(rowbase + row, Bsz - 1);
        float hv = state_h[(size_t)b * Hh + k];
        sh_h_my[k * HSTR + row] = hv;
        sh_h_ff[k * HSTR + row] = hv;
    }
    if (tid < ROWS) {
        int row = tid;
        int b = min(rowbase + row, Bsz - 1);
        float m0 = cond_m[((size_t)b * Tt) * 2 + 0];
        float m1 = cond_m[((size_t)b * Tt) * 2 + 1];
        float y0 = cond_y[(size_t)b * Tt];
        float f0 = cond_f[(size_t)b * Tt];
        float a0 = cond_fa[(size_t)b * Tt];
        sh_cond5[0 * HSTR + row] = m0;
        sh_cond5[1 * HSTR + row] = m1;
        sh_cond5[2 * HSTR + row] = y0;
        sh_cond5[3 * HSTR + row] = f0;
        sh_cond5[4 * HSTR + row] = a0;
        sh_cond2[0 * HSTR + row] = f0;
        sh_cond2[1 * HSTR + row] = a0;
    }

    // ---- c state in registers, encW pair indices ----
    float cmy[14], cff[14];
    int epair[7];
#pragma unroll
    for (int r = 0; r < 14; r++) {
        int b = min(rowbase + rbl + r, Bsz - 1);
        float cv = state_c[(size_t)b * Hh + j];
        cmy[r] = cv; cff[r] = cv;
    }
#pragma unroll
    for (int p = 0; p < 7; p++)
        epair[p] = min(rowbase + rbl + 2 * p, Bsz - 2) >> 1;

    // head-phase mapping: 150 active threads, c=tid%75, half=tid/75
    const int hc = tid % 75;
    const int hhalf = tid / 75;
    const bool hact = tid < 150;
    float hbias = 0.0f;
    if (hact) hbias = (hc < 45) ? bh_my[hc] : bh_ff[hc - 45];

    float* out_gm  = out;
    float* out_gy  = out + (size_t)Bsz * Tt * 30;
    float* out_gf  = out + (size_t)Bsz * Tt * 45;
    float* out_gfa = out + (size_t)Bsz * Tt * 60;

    __syncthreads();

    for (int t = 0; t < Tt; t++) {
        // phase-parity ordering: the two LSTMs are independent within a step
        if (swap) {
            lstm_phase<2>(g_encW_ff, g_Ut_ff, W_ff, sh_cond2, sh_h_ff, sh_U, cff, j, rbl, epair, tid);
            lstm_phase<5>(g_encW_my, g_Ut_my, W_my, sh_cond5, sh_h_my, sh_U, cmy, j, rbl, epair, tid);
        } else {
            lstm_phase<5>(g_encW_my, g_Ut_my, W_my, sh_cond5, sh_h_my, sh_U, cmy, j, rbl, epair, tid);
            lstm_phase<2>(g_encW_ff, g_Ut_ff, W_ff, sh_cond2, sh_h_ff, sh_U, cff, j, rbl, epair, tid);
        }
        __syncthreads();  // h_my / h_ff visible

        // ===== heads: Wht row-contiguous LDG.128, h pairs from smem =====
        if (hact) {
            const float* hb = ((hc < 45) ? sh_h_my : sh_h_ff) + hhalf * 14;
            const float4* wr = (const float4*)(g_Wht + hc * Hh);
            u64 a[7];
            u64 binit = dup2f(hbias);
#pragma unroll
            for (int p = 0; p < 7; p++) a[p] = binit;
#pragma unroll 8
            for (int k4 = 0; k4 < Hh / 4; k4++) {
                float4 w4 = __ldg(&wr[k4]);
                const float* hk = hb + (4 * k4) * HSTR;
                u64 w0 = dup2f(w4.x);
                u64 w1 = dup2f(w4.y);
                u64 w2 = dup2f(w4.z);
                u64 w3 = dup2f(w4.w);
#pragma unroll
                for (int p = 0; p < 7; p++) {
                    fma2(a[p], *(const u64*)(hk + 2 * p), w0);
                    fma2(a[p], *(const u64*)(hk + HSTR + 2 * p), w1);
                    fma2(a[p], *(const u64*)(hk + 2 * HSTR + 2 * p), w2);
                    fma2(a[p], *(const u64*)(hk + 3 * HSTR + 2 * p), w3);
                }
            }
#pragma unroll
            for (int p = 0; p < 7; p++) {
                float v0, v1;
                unpack2(a[p], v0, v1);
                int row = hhalf * 14 + 2 * p;
                sh_r[row * 76 + hc] = v0;
                sh_r[(row + 1) * 76 + hc] = v1;
            }
        }
        __syncthreads();

        // ===== sampling / cond update / outputs =====
        if (tid < 4 * ROWS) {
            const int row = tid >> 2;
            const int d = tid & 3;
            const bool valid = (rowbase + row) < Bsz;
            const int b = min(rowbase + row, Bsz - 1);
            const int tn = min(t + 1, Tt - 1);
            const float* gum = gumbel + (((size_t)t * 4 + d) * Bsz + b) * KcK;
            const float* zn = znorm + ((size_t)t * Bsz + b) * 5;

            if (d == 0) {
                const float* rb = sh_r + row * 76;
                float lg[5], mul[5], sl[5], mulat[5], slat[5], rho[5];
#pragma unroll
                for (int k = 0; k < 5; k++) {
                    lg[k]    = rb[k];
                    mul[k]   = rb[5 + k];
                    sl[k]    = expf_fast(rb[10 + k]);
                    mulat[k] = rb[15 + k];
                    slat[k]  = expf_fast(rb[20 + k]);
                    rho[k]   = tanhf_fast(rb[25 + k]);
                }
                float mx = lg[0];
#pragma unroll
                for (int k = 1; k < 5; k++) mx = fmaxf(mx, lg[k]);
                float am[5], ssum = 0.0f;
#pragma unroll
                for (int k = 0; k < 5; k++) { am[k] = expf_fast(lg[k] - mx); ssum += am[k]; }
                float inv = 1.0f / ssum;
#pragma unroll
                for (int k = 0; k < 5; k++) am[k] *= inv;
                int im = 0; float best = lg[0] + gum[0];
#pragma unroll
                for (int k = 1; k < 5; k++) {
                    float v = lg[k] + gum[k];
                    if (v > best) { best = v; im = k; }
                }
                float z1 = zn[0], z2 = zn[1];
                float rr = rho[im];
                float s_long = mul[im] + sl[im] * z1;
                float s_lt = mulat[im] + slat[im] * (rr * z1 + sqrtf(fmaxf(1.0f - rr * rr, 0.0f)) * z2);
                float nm0 = cond_m[((size_t)b * Tt + tn) * 2 + 0];
                float nm1 = cond_m[((size_t)b * Tt + tn) * 2 + 1];
                sh_cond5[0 * HSTR + row] = (fabsf(s_long - nm0) < 0.3f) ? s_long : nm0;
                sh_cond5[1 * HSTR + row] = (fabsf(s_lt  - nm1) < 0.1f) ? s_lt  : nm1;
                if (valid) {
                    float* o = out_gm + ((size_t)b * Tt + t) * 30;
#pragma unroll
                    for (int k = 0; k < 5; k++) {
                        o[k] = am[k]; o[5 + k] = mul[k]; o[10 + k] = sl[k];
                        o[15 + k] = mulat[k]; o[20 + k] = slat[k]; o[25 + k] = rho[k];
                    }
                }
            } else {
                const float* rb;
                float zv, nv;
                float* osec;
                if (d == 1) {
                    rb = sh_r + row * 76 + 30; zv = zn[2];
                    nv = cond_y[(size_t)b * Tt + tn]; osec = out_gy;
                } else if (d == 2) {
                    rb = sh_r + row * 76 + 45; zv = zn[3];
                    nv = cond_f[(size_t)b * Tt + tn]; osec = out_gf;
                } else {
                    rb = sh_r + row * 76 + 60; zv = zn[4];
                    nv = cond_fa[(size_t)b * Tt + tn]; osec = out_gfa;
                }
                float lg[5], mu[5], s[5];
#pragma unroll
                for (int k = 0; k < 5; k++) {
                    lg[k] = rb[k]; mu[k] = rb[5 + k]; s[k] = expf_fast(rb[10 + k]);
                }
                float mx = lg[0];
#pragma unroll
                for (int k = 1; k < 5; k++) mx = fmaxf(mx, lg[k]);
                float am[5], ssum = 0.0f;
#pragma unroll
                for (int k = 0; k < 5; k++) { am[k] = expf_fast(lg[k] - mx); ssum += am[k]; }
                float inv = 1.0f / ssum;
#pragma unroll
                for (int k = 0; k < 5; k++) am[k] *= inv;
                int im = 0; float best = lg[0] + gum[0];
#pragma unroll
                for (int k = 1; k < 5; k++) {
                    float v = lg[k] + gum[k];
                    if (v > best) { best = v; im = k; }
                }
                float samp = mu[im] + s[im] * zv;
                float cn = (fabsf(samp - nv) < 0.3f) ? samp : nv;
                if (d == 1) {
                    sh_cond5[2 * HSTR + row] = cn;
                } else if (d == 2) {
                    sh_cond5[3 * HSTR + row] = cn;
                    sh_cond2[0 * HSTR + row] = cn;
                } else {
                    sh_cond5[4 * HSTR + row] = cn;
                    sh_cond2[1 * HSTR + row] = cn;
                }
                if (valid) {
                    float* o = osec + ((size_t)b * Tt + t) * 15;
#pragma unroll
                    for (int k = 0; k < 5; k++) {
                        o[k] = am[k]; o[5 + k] = mu[k]; o[10 + k] = s[k];
                    }
                }
            }
        }
        __syncthreads();  // cond updated for next step
    }
}

// ---------------------------------------------------------------------------
extern "C" void kernel_launch(void* const* d_in, const int* in_sizes, int n_in,
                              void* d_out, int out_size)
{
    (void)in_sizes; (void)n_in; (void)out_size;
    const float* cond_m  = (const float*)d_in[0];
    const float* cond_y  = (const float*)d_in[1];
    const float* cond_f  = (const float*)d_in[2];
    const float* cond_fa = (const float*)d_in[3];
    const float* state_h = (const float*)d_in[4];
    const float* state_c = (const float*)d_in[5];
    const float* W_my    = (const float*)d_in[6];
    const float* U_my    = (const float*)d_in[7];
    const float* b_my    = (const float*)d_in[8];
    const float* W_ff    = (const float*)d_in[9];
    const float* U_ff    = (const float*)d_in[10];
    const float* b_ff    = (const float*)d_in[11];
    const float* Wh_my   = (const float*)d_in[12];
    const float* bh_my   = (const float*)d_in[13];
    const float* Wh_ff   = (const float*)d_in[14];
    const float* bh_ff   = (const float*)d_in[15];
    const float* gumbel  = (const float*)d_in[16];
    const float* znorm   = (const float*)d_in[17];
    float* out = (float*)d_out;

    const int smem_floats = 2 * KCH * NG + 2 * Hh * HSTR + 7 * HSTR + ROWS * 76;
    const int smem_bytes = smem_floats * (int)sizeof(float);  // ~105.6 KB

    cudaFuncSetAttribute(decoder_kernel,
                         cudaFuncAttributeMaxDynamicSharedMemorySize, smem_bytes);

    precompute_kernel<<<Bsz / PRE_BB, 256>>>(state_h, W_my, b_my, W_ff, b_ff,
                                             U_my, U_ff, Wh_my, Wh_ff);
    decoder_kernel<<<NCTA, NTHREADS, smem_bytes>>>(
        cond_m, cond_y, cond_f, cond_fa, state_h, state_c,
        W_my, W_ff, bh_my, bh_ff, gumbel, znorm, out);
}

// round 6
// speedup vs baseline: 1.0832x; 1.0568x over previous
#include <cuda_runtime.h>
#include <cuda_bf16.h>

// ---------------------------------------------------------------------------
// Decoder_65111704207909  (B=8192, T=20, H=128, K=5)
// Round 6: 1 CTA/SM x 512 thr, 56 rows/CTA, grid=147 (one even wave).
//  - h stored [k][phys_row], HSTR=68, group bases {0,16,32,48} (16B aligned)
//    -> broadcast h reads as 3x LDS.128 + 1x LDS.64 (4 wf vs 7 per kk)
//  - heads on 300 threads with the same LDS.128 broadcast reads
//  - KCH=16 double-buffered cp.async U staging, 1 barrier per chunk
//  - encW pair-packed (LDG.64 acc init), U gate-interleaved, Wh transposed
// ---------------------------------------------------------------------------

#define Bsz 8192
#define Tt 20
#define Hh 128
#define KcK 5
#define NG 512                    // 4*H
#define ROWS 56
#define NCTA 147
#define NTHREADS 512
#define HSTR 68                   // phys row stride (272B: 16B-multiple)
#define CSTR 64                   // cond stride
#define KCH 16                    // k-rows per staged chunk
#define NCHUNK (Hh / KCH)         // 8
#define PRE_BB 16

typedef unsigned long long u64;

// enc_h @ W[:H] + b (bias folded), pair-packed: [(b>>1)][col][b&1]
__device__ float g_encW_my[(size_t)Bsz * NG];
__device__ float g_encW_ff[(size_t)Bsz * NG];
// U transposed: [k][j][g]  (g = gate 0..3, contiguous)
__device__ float g_Ut_my[(size_t)Hh * NG];
__device__ float g_Ut_ff[(size_t)Hh * NG];
// Wh transposed: [c][k]
__device__ float g_Wht[75 * Hh];

__device__ __forceinline__ u64 pack2f(float x, float y) {
    u64 r; asm("mov.b64 %0, {%1, %2};" : "=l"(r) : "f"(x), "f"(y)); return r;
}
__device__ __forceinline__ u64 dup2f(float x) {
    u64 r; asm("mov.b64 %0, {%1, %1};" : "=l"(r) : "f"(x)); return r;
}
__device__ __forceinline__ void fma2(u64& d, u64 a, u64 b) {
    asm("fma.rn.f32x2 %0, %1, %2, %0;" : "+l"(d) : "l"(a), "l"(b));
}
__device__ __forceinline__ void unpack2(u64 v, float& x, float& y) {
    asm("mov.b64 {%0, %1}, %2;" : "=f"(x), "=f"(y) : "l"(v));
}

// ---- fast transcendentals ----
__device__ __forceinline__ float ex2f(float x) {
    float y; asm("ex2.approx.f32 %0, %1;" : "=f"(y) : "f"(x)); return y;
}
__device__ __forceinline__ float rcpf(float x) {
    float y; asm("rcp.approx.f32 %0, %1;" : "=f"(y) : "f"(x)); return y;
}
#define LOG2E 1.4426950408889634f
__device__ __forceinline__ float sigf(float x) {
    return rcpf(1.0f + ex2f(-LOG2E * x));
}
__device__ __forceinline__ float tanhf_fast(float x) {
    return fmaf(-2.0f, rcpf(1.0f + ex2f((2.0f * LOG2E) * x)), 1.0f);
}
__device__ __forceinline__ float expf_fast(float x) { return ex2f(LOG2E * x); }

// logical row -> physical row (14-row groups at 16-row phys pitch)
__device__ __forceinline__ int physrow(int r) { return (r / 14) * 16 + (r % 14); }

// ---- cp.async: one chunk = KCH*NG floats = 32KB = 512 thr x 4 x 16B ----
__device__ __forceinline__ void stage_chunk(float* dst, const float* __restrict__ src, int tid) {
    unsigned smp = (unsigned)__cvta_generic_to_shared(dst);
#pragma unroll
    for (int i = 0; i < 4; i++) {
        asm volatile("cp.async.cg.shared.global [%0], [%1], 16;"
                     :: "r"(smp + (unsigned)((tid + i * NTHREADS) * 16)),
                        "l"(src + (size_t)(tid + i * NTHREADS) * 4)
                     : "memory");
    }
    asm volatile("cp.async.commit_group;" ::: "memory");
}
template <int N>
__device__ __forceinline__ void cp_wait() {
    asm volatile("cp.async.wait_group %0;" :: "n"(N) : "memory");
}

// ---------------------------------------------------------------------------
// Precompute: g_encW = state_h @ W[:H,:] + b (pair-packed) + folded transposes
// ---------------------------------------------------------------------------
__global__ __launch_bounds__(256) void precompute_kernel(
    const float* __restrict__ state_h,
    const float* __restrict__ W_my, const float* __restrict__ b_my,
    const float* __restrict__ W_ff, const float* __restrict__ b_ff,
    const float* __restrict__ U_my, const float* __restrict__ U_ff,
    const float* __restrict__ Wh_my, const float* __restrict__ Wh_ff)
{
    const int t = threadIdx.x;

    // folded transposes (blocks 0..255 cover Hh*NG = 65536 elems)
    {
        int gidx = blockIdx.x * 256 + t;
        if (gidx < Hh * NG) {
            int k = gidx >> 9;
            int r = gidx & 511;
            int j = r >> 2, g = r & 3;
            g_Ut_my[gidx] = U_my[(size_t)k * NG + g * 128 + j];
            g_Ut_ff[gidx] = U_ff[(size_t)k * NG + g * 128 + j];
        }
        if (gidx < 75 * Hh) {
            int c = gidx >> 7, k = gidx & 127;
            g_Wht[gidx] = (c < 45) ? Wh_my[(size_t)k * 45 + c]
                                   : Wh_ff[(size_t)k * 30 + (c - 45)];
        }
    }

    __shared__ float hsh[Hh * PRE_BB];  // [k][bb]
    const int b0 = blockIdx.x * PRE_BB;

    for (int idx = t; idx < Hh * PRE_BB; idx += 256) {
        int k = idx / PRE_BB, bb = idx % PRE_BB;
        hsh[idx] = state_h[(size_t)(b0 + bb) * Hh + k];
    }
    __syncthreads();

    const int c0 = 2 * t;
    u64 accm[PRE_BB], accf[PRE_BB];
    u64 bm = pack2f(b_my[c0], b_my[c0 + 1]);
    u64 bf = pack2f(b_ff[c0], b_ff[c0 + 1]);
#pragma unroll
    for (int bb = 0; bb < PRE_BB; bb++) { accm[bb] = bm; accf[bb] = bf; }

    for (int k = 0; k < Hh; k++) {
        u64 wm = *(const u64*)&W_my[(size_t)k * NG + c0];
        u64 wf = *(const u64*)&W_ff[(size_t)k * NG + c0];
#pragma unroll
        for (int bb = 0; bb < PRE_BB; bb++) {
            u64 hh = dup2f(hsh[k * PRE_BB + bb]);
            fma2(accm[bb], hh, wm);
            fma2(accf[bb], hh, wf);
        }
    }
#pragma unroll
    for (int bb = 0; bb < PRE_BB; bb++) {
        int b = b0 + bb;
        size_t base = ((size_t)(b >> 1) * NG) * 2 + (b & 1);
        float v0, v1;
        unpack2(accm[bb], v0, v1);
        g_encW_my[base + 2 * (size_t)c0] = v0;
        g_encW_my[base + 2 * (size_t)(c0 + 1)] = v1;
        unpack2(accf[bb], v0, v1);
        g_encW_ff[base + 2 * (size_t)c0] = v0;
        g_encW_ff[base + 2 * (size_t)(c0 + 1)] = v1;
    }
}

// ---------------------------------------------------------------------------
// One LSTM update for 56 rows with 512 threads.
// Thread (j = tid&127, g = tid>>7): gate cols {j,j+128,j+256,j+384},
// logical rows g*14..g*14+13 at phys base g*16 (7 packed row-pairs).
// h reads: 3x LDS.128 + 1x LDS.64, all warp-broadcast.
// ---------------------------------------------------------------------------
template <int NQ>
__device__ __forceinline__ void lstm_phase(
    const float* __restrict__ encW,   // pair-packed
    const float* __restrict__ Ut,     // gate-interleaved [k][j][g]
    const float* __restrict__ Wg,     // W matrix (tail rows H.. used)
    const float* sh_cond, float* sh_h, float* sh_U,
    float (&c)[14], int j, int rphys, const int* epair, int tid)
{
    stage_chunk(sh_U, Ut, tid);

    // ---- acc init: encW (bias folded, LDG.64) + cond-tail @ W[H:, :] ----
    u64 acc[4][7];
#pragma unroll
    for (int g4 = 0; g4 < 4; g4++) {
        const int col = g4 * 128 + j;
#pragma unroll
        for (int p = 0; p < 7; p++)
            acc[g4][p] = *(const u64*)&encW[((size_t)epair[p] * NG + col) * 2];
    }
#pragma unroll
    for (int q = 0; q < NQ; q++) {
        u64 cpp[7];
#pragma unroll
        for (int p = 0; p < 7; p++)
            cpp[p] = *(const u64*)(sh_cond + q * CSTR + rphys + 2 * p);
#pragma unroll
        for (int g4 = 0; g4 < 4; g4++) {
            u64 wd = dup2f(__ldg(&Wg[(size_t)(Hh + q) * NG + g4 * 128 + j]));
#pragma unroll
            for (int p = 0; p < 7; p++) fma2(acc[g4][p], cpp[p], wd);
        }
    }

    // ---- main GEMM, double buffer, one barrier per chunk ----
    for (int ch = 0; ch < NCHUNK; ch++) {
        cp_wait<0>();
        __syncthreads();   // chunk ch visible; all warps past compute(ch-1)
        if (ch + 1 < NCHUNK)
            stage_chunk(sh_U + ((ch + 1) & 1) * KCH * NG,
                        Ut + (size_t)(ch + 1) * KCH * NG, tid);
        const float* ub = sh_U + (ch & 1) * KCH * NG + 4 * j;
        const float* hb = sh_h + (ch * KCH) * HSTR + rphys;
#pragma unroll
        for (int kk = 0; kk < KCH; kk++) {
            float4 uu = *(const float4*)(ub + kk * NG);
            u64 u0 = dup2f(uu.x);
            u64 u1 = dup2f(uu.y);
            u64 u2 = dup2f(uu.z);
            u64 u3 = dup2f(uu.w);
            const float* hk = hb + kk * HSTR;
            ulonglong2 h01 = *(const ulonglong2*)(hk);
            ulonglong2 h23 = *(const ulonglong2*)(hk + 4);
            ulonglong2 h45 = *(const ulonglong2*)(hk + 8);
            u64 h6 = *(const u64*)(hk + 12);
            u64 hp[7] = { h01.x, h01.y, h23.x, h23.y, h45.x, h45.y, h6 };
#pragma unroll
            for (int p = 0; p < 7; p++) {
                u64 h2 = hp[p];
                fma2(acc[0][p], h2, u0);
                fma2(acc[1][p], h2, u1);
                fma2(acc[2][p], h2, u2);
                fma2(acc[3][p], h2, u3);
            }
        }
    }
    __syncthreads();  // all threads done reading old sh_h

    // ---- gates; c register-private ----
#pragma unroll
    for (int p = 0; p < 7; p++) {
        float zi0, zi1, zf0, zf1, zg0, zg1, zo0, zo1;
        unpack2(acc[0][p], zi0, zi1);
        unpack2(acc[1][p], zf0, zf1);
        unpack2(acc[2][p], zg0, zg1);
        unpack2(acc[3][p], zo0, zo1);
        float c20 = sigf(zf0) * c[2 * p]     + sigf(zi0) * tanhf_fast(zg0);
        float c21 = sigf(zf1) * c[2 * p + 1] + sigf(zi1) * tanhf_fast(zg1);
        c[2 * p] = c20; c[2 * p + 1] = c21;
        *(u64*)(sh_h + j * HSTR + rphys + 2 * p) =
            pack2f(sigf(zo0) * tanhf_fast(c20), sigf(zo1) * tanhf_fast(c21));
    }
}

// ---------------------------------------------------------------------------
__global__ __launch_bounds__(NTHREADS, 1) void decoder_kernel(
    const float* __restrict__ cond_m, const float* __restrict__ cond_y,
    const float* __restrict__ cond_f, const float* __restrict__ cond_fa,
    const float* __restrict__ state_h, const float* __restrict__ state_c,
    const float* __restrict__ W_my, const float* __restrict__ W_ff,
    const float* __restrict__ bh_my, const float* __restrict__ bh_ff,
    const float* __restrict__ gumbel, const float* __restrict__ znorm,
    float* __restrict__ out)
{
    extern __shared__ float smem[];
    float* sh_U     = smem;                       // 2*KCH*NG = 16384 floats
    float* sh_h_my  = sh_U + 2 * KCH * NG;        // Hh*HSTR
    float* sh_h_ff  = sh_h_my + Hh * HSTR;
    float* sh_cond5 = sh_h_ff + Hh * HSTR;        // [q][CSTR] (phys rows)
    float* sh_cond2 = sh_cond5 + 5 * CSTR;
    float* sh_r     = sh_cond2 + 2 * CSTR;        // [logical row][76]

    const int tid = threadIdx.x;
    const int rowbase = blockIdx.x * ROWS;
    const int j = tid & 127;
    const int g = tid >> 7;        // 0..3
    const int rlog = g * 14;
    const int rphys = g * 16;

    // ---- init h and cond ----
    for (int idx = tid; idx < Hh * ROWS; idx += NTHREADS) {
        int k = idx / ROWS, row = idx % ROWS;
        int b = min(rowbase + row, Bsz - 1);
        float hv = state_h[(size_t)b * Hh + k];
        int pr = physrow(row);
        sh_h_my[k * HSTR + pr] = hv;
        sh_h_ff[k * HSTR + pr] = hv;
    }
    if (tid < ROWS) {
        int row = tid;
        int pr = physrow(row);
        int b = min(rowbase + row, Bsz - 1);
        float m0 = cond_m[((size_t)b * Tt) * 2 + 0];
        float m1 = cond_m[((size_t)b * Tt) * 2 + 1];
        float y0 = cond_y[(size_t)b * Tt];
        float f0 = cond_f[(size_t)b * Tt];
        float a0 = cond_fa[(size_t)b * Tt];
        sh_cond5[0 * CSTR + pr] = m0;
        sh_cond5[1 * CSTR + pr] = m1;
        sh_cond5[2 * CSTR + pr] = y0;
        sh_cond5[3 * CSTR + pr] = f0;
        sh_cond5[4 * CSTR + pr] = a0;
        sh_cond2[0 * CSTR + pr] = f0;
        sh_cond2[1 * CSTR + pr] = a0;
    }

    // ---- c state in registers, encW pair indices (logical rows) ----
    float cmy[14], cff[14];
    int epair[7];
#pragma unroll
    for (int r = 0; r < 14; r++) {
        int b = min(rowbase + rlog + r, Bsz - 1);
        float cv = state_c[(size_t)b * Hh + j];
        cmy[r] = cv; cff[r] = cv;
    }
#pragma unroll
    for (int p = 0; p < 7; p++)
        epair[p] = min(rowbase + rlog + 2 * p, Bsz - 2) >> 1;

    // head-phase mapping: 300 active threads, c=tid%75, quarter=tid/75
    const int hc = tid % 75;
    const int hq = tid / 75;       // 0..3 row group
    const bool hact = tid < 300;
    float hbias = 0.0f;
    if (hact) hbias = (hc < 45) ? bh_my[hc] : bh_ff[hc - 45];

    float* out_gm  = out;
    float* out_gy  = out + (size_t)Bsz * Tt * 30;
    float* out_gf  = out + (size_t)Bsz * Tt * 45;
    float* out_gfa = out + (size_t)Bsz * Tt * 60;

    __syncthreads();

    for (int t = 0; t < Tt; t++) {
        lstm_phase<5>(g_encW_my, g_Ut_my, W_my, sh_cond5, sh_h_my, sh_U, cmy, j, rphys, epair, tid);
        lstm_phase<2>(g_encW_ff, g_Ut_ff, W_ff, sh_cond2, sh_h_ff, sh_U, cff, j, rphys, epair, tid);
        __syncthreads();  // h_my / h_ff visible

        // ===== heads: Wht LDG.128, h via broadcast LDS.128 =====
        if (hact) {
            const float* hb = ((hc < 45) ? sh_h_my : sh_h_ff) + hq * 16;
            const float4* wr = (const float4*)(g_Wht + hc * Hh);
            u64 a[7];
            u64 binit = dup2f(hbias);
#pragma unroll
            for (int p = 0; p < 7; p++) a[p] = binit;
#pragma unroll 4
            for (int k4 = 0; k4 < Hh / 4; k4++) {
                float4 w4 = __ldg(&wr[k4]);
                float wv[4] = { w4.x, w4.y, w4.z, w4.w };
#pragma unroll
                for (int kk = 0; kk < 4; kk++) {
                    const float* hk = hb + (4 * k4 + kk) * HSTR;
                    ulonglong2 h01 = *(const ulonglong2*)(hk);
                    ulonglong2 h23 = *(const ulonglong2*)(hk + 4);
                    ulonglong2 h45 = *(const ulonglong2*)(hk + 8);
                    u64 h6 = *(const u64*)(hk + 12);
                    u64 wd = dup2f(wv[kk]);
                    fma2(a[0], h01.x, wd);
                    fma2(a[1], h01.y, wd);
                    fma2(a[2], h23.x, wd);
                    fma2(a[3], h23.y, wd);
                    fma2(a[4], h45.x, wd);
                    fma2(a[5], h45.y, wd);
                    fma2(a[6], h6, wd);
                }
            }
#pragma unroll
            for (int p = 0; p < 7; p++) {
                float v0, v1;
                unpack2(a[p], v0, v1);
                int row = hq * 14 + 2 * p;     // logical row
                sh_r[row * 76 + hc] = v0;
                sh_r[(row + 1) * 76 + hc] = v1;
            }
        }
        __syncthreads();

        // ===== sampling / cond update / outputs =====
        if (tid < 4 * ROWS) {
            const int row = tid >> 2;          // logical row
            const int pr = physrow(row);
            const int d = tid & 3;
            const bool valid = (rowbase + row) < Bsz;
            const int b = min(rowbase + row, Bsz - 1);
            const int tn = min(t + 1, Tt - 1);
            const float* gum = gumbel + (((size_t)t * 4 + d) * Bsz + b) * KcK;
            const float* zn = znorm + ((size_t)t * Bsz + b) * 5;

            if (d == 0) {
                const float* rb = sh_r + row * 76;
                float lg[5], mul[5], sl[5], mulat[5], slat[5], rho[5];
#pragma unroll
                for (int k = 0; k < 5; k++) {
                    lg[k]    = rb[k];
                    mul[k]   = rb[5 + k];
                    sl[k]    = expf_fast(rb[10 + k]);
                    mulat[k] = rb[15 + k];
                    slat[k]  = expf_fast(rb[20 + k]);
                    rho[k]   = tanhf_fast(rb[25 + k]);
                }
                float mx = lg[0];
#pragma unroll
                for (int k = 1; k < 5; k++) mx = fmaxf(mx, lg[k]);
                float am[5], ssum = 0.0f;
#pragma unroll
                for (int k = 0; k < 5; k++) { am[k] = expf_fast(lg[k] - mx); ssum += am[k]; }
                float inv = 1.0f / ssum;
#pragma unroll
                for (int k = 0; k < 5; k++) am[k] *= inv;
                int im = 0; float best = lg[0] + gum[0];
#pragma unroll
                for (int k = 1; k < 5; k++) {
                    float v = lg[k] + gum[k];
                    if (v > best) { best = v; im = k; }
                }
                float z1 = zn[0], z2 = zn[1];
                float rr = rho[im];
                float s_long = mul[im] + sl[im] * z1;
                float s_lt = mulat[im] + slat[im] * (rr * z1 + sqrtf(fmaxf(1.0f - rr * rr, 0.0f)) * z2);
                float nm0 = cond_m[((size_t)b * Tt + tn) * 2 + 0];
                float nm1 = cond_m[((size_t)b * Tt + tn) * 2 + 1];
                sh_cond5[0 * CSTR + pr] = (fabsf(s_long - nm0) < 0.3f) ? s_long : nm0;
                sh_cond5[1 * CSTR + pr] = (fabsf(s_lt  - nm1) < 0.1f) ? s_lt  : nm1;
                if (valid) {
                    float* o = out_gm + ((size_t)b * Tt + t) * 30;
#pragma unroll
                    for (int k = 0; k < 5; k++) {
                        o[k] = am[k]; o[5 + k] = mul[k]; o[10 + k] = sl[k];
                        o[15 + k] = mulat[k]; o[20 + k] = slat[k]; o[25 + k] = rho[k];
                    }
                }
            } else {
                const float* rb;
                float zv, nv;
                float* osec;
                if (d == 1) {
                    rb = sh_r + row * 76 + 30; zv = zn[2];
                    nv = cond_y[(size_t)b * Tt + tn]; osec = out_gy;
                } else if (d == 2) {
                    rb = sh_r + row * 76 + 45; zv = zn[3];
                    nv = cond_f[(size_t)b * Tt + tn]; osec = out_gf;
                } else {
                    rb = sh_r + row * 76 + 60; zv = zn[4];
                    nv = cond_fa[(size_t)b * Tt + tn]; osec = out_gfa;
                }
                float lg[5], mu[5], s[5];
#pragma unroll
                for (int k = 0; k < 5; k++) {
                    lg[k] = rb[k]; mu[k] = rb[5 + k]; s[k] = expf_fast(rb[10 + k]);
                }
                float mx = lg[0];
#pragma unroll
                for (int k = 1; k < 5; k++) mx = fmaxf(mx, lg[k]);
                float am[5], ssum = 0.0f;
#pragma unroll
                for (int k = 0; k < 5; k++) { am[k] = expf_fast(lg[k] - mx); ssum += am[k]; }
                float inv = 1.0f / ssum;
#pragma unroll
                for (int k = 0; k < 5; k++) am[k] *= inv;
                int im = 0; float best = lg[0] + gum[0];
#pragma unroll
                for (int k = 1; k < 5; k++) {
                    float v = lg[k] + gum[k];
                    if (v > best) { best = v; im = k; }
                }
                float samp = mu[im] + s[im] * zv;
                float cn = (fabsf(samp - nv) < 0.3f) ? samp : nv;
                if (d == 1) {
                    sh_cond5[2 * CSTR + pr] = cn;
                } else if (d == 2) {
                    sh_cond5[3 * CSTR + pr] = cn;
                    sh_cond2[0 * CSTR + pr] = cn;
                } else {
                    sh_cond5[4 * CSTR + pr] = cn;
                    sh_cond2[1 * CSTR + pr] = cn;
                }
                if (valid) {
                    float* o = osec + ((size_t)b * Tt + t) * 15;
#pragma unroll
                    for (int k = 0; k < 5; k++) {
                        o[k] = am[k]; o[5 + k] = mu[k]; o[10 + k] = s[k];
                    }
                }
            }
        }
        __syncthreads();  // cond updated for next step
    }
}

// ---------------------------------------------------------------------------
extern "C" void kernel_launch(void* const* d_in, const int* in_sizes, int n_in,
                              void* d_out, int out_size)
{
    (void)in_sizes; (void)n_in; (void)out_size;
    const float* cond_m  = (const float*)d_in[0];
    const float* cond_y  = (const float*)d_in[1];
    const float* cond_f  = (const float*)d_in[2];
    const float* cond_fa = (const float*)d_in[3];
    const float* state_h = (const float*)d_in[4];
    const float* state_c = (const float*)d_in[5];
    const float* W_my    = (const float*)d_in[6];
    const float* U_my    = (const float*)d_in[7];
    const float* b_my    = (const float*)d_in[8];
    const float* W_ff    = (const float*)d_in[9];
    const float* U_ff    = (const float*)d_in[10];
    const float* b_ff    = (const float*)d_in[11];
    const float* Wh_my   = (const float*)d_in[12];
    const float* bh_my   = (const float*)d_in[13];
    const float* Wh_ff   = (const float*)d_in[14];
    const float* bh_ff   = (const float*)d_in[15];
    const float* gumbel  = (const float*)d_in[16];
    const float* znorm   = (const float*)d_in[17];
    float* out = (float*)d_out;

    const int smem_floats = 2 * KCH * NG + 2 * Hh * HSTR + 7 * CSTR + ROWS * 76;
    const int smem_bytes = smem_floats * (int)sizeof(float);  // ~154 KB

    cudaFuncSetAttribute(decoder_kernel,
                         cudaFuncAttributeMaxDynamicSharedMemorySize, smem_bytes);

    precompute_kernel<<<Bsz / PRE_BB, 256>>>(state_h, W_my, b_my, W_ff, b_ff,
                                             U_my, U_ff, Wh_my, Wh_ff);
    decoder_kernel<<<NCTA, NTHREADS, smem_bytes>>>(
        cond_m, cond_y, cond_f, cond_fa, state_h, state_c,
        W_my, W_ff, bh_my, bh_ff, gumbel, znorm, out);
}